// round 2
// baseline (speedup 1.0000x reference)
#include <cuda_runtime.h>
#include <math.h>

// ---------------- problem constants ----------------
#define NB      32          // batch
#define FH      11          // fmap h
#define FW      20          // fmap w
#define NEDGE   42          // FW + 2*FH
#define NANG    17
#define NPRED   77          // 2+2+1+72
#define NPROP   714         // NEDGE * NANG
#define NOFF    72
#define KBACK   512
#define KCONV   1024
#define NREG    1241        // 17*73
#define NCLS    34          // 17*2
#define MROWS   1344        // NB * NEDGE
#define NWORDS  23          // ceil(714/32)
#define NSTRIPSF 71.0f
#define NMS_T   15.0f

// ---------------- scratch (no allocations allowed) ----------------
__device__ float    g_featET[KBACK * MROWS];        // A^T for GEMM1 (K x M)
__device__ float    g_convT [KCONV * MROWS];        // features^T (K x M) for GEMM2/3
__device__ float    g_reg   [MROWS * NREG];         // reg outputs, row-major
__device__ float    g_cls   [MROWS * NCLS];         // cls outputs, row-major
__device__ int      g_order [NB * NPROP];           // sorted->orig index
__device__ float    g_sstart[NB * NPROP];           // sorted start
__device__ float    g_send  [NB * NPROP];           // sorted end
__device__ float    g_sxs   [NB * NPROP * NOFF];    // sorted xs
__device__ unsigned g_sup   [NB * NPROP * NWORDS];  // suppression bitmatrix

// ---------------- gather edge features into A^T layout ----------------
__global__ void k_gather(const float* __restrict__ feat) {
    int x = blockIdx.x * blockDim.x + threadIdx.x;
    if (x >= KBACK * MROWS) return;
    int m = x % MROWS;
    int c = x / MROWS;
    int b = m / NEDGE, e = m % NEDGE;
    int h, w;
    if (e < FH)        { h = e;      w = 0;        }
    else if (e < 2*FH) { h = e - FH; w = FW - 1;   }
    else               { h = FH - 1; w = e - 2*FH; }
    g_featET[x] = feat[((size_t)(b * KBACK + c) * FH + h) * FW + w];
}

// ---------------- fp32 GEMM using packed fma.rn.f32x2 ----------------
// C[m][n] = sum_k AT[k][m] * W[n][k] + bias[n]
// tile 64(M) x 128(N) x 16(K), 256 threads, 4x8 microtile as 4x4 f32x2 pairs
template<int TRANS_OUT>
__global__ __launch_bounds__(256) void k_gemm(
    const float* __restrict__ AT, const float* __restrict__ W,
    const float* __restrict__ bias, float* __restrict__ C,
    int K, int N)
{
    __shared__ float As[16][64];
    __shared__ float Bs[16][132];   // +4 pad keeps 16B alignment, reduces conflicts
    const int m0 = blockIdx.y * 64;
    const int n0 = blockIdx.x * 128;
    const int t  = threadIdx.x;
    const int tx = t & 15, ty = t >> 4;

    unsigned long long acc[4][4];
#pragma unroll
    for (int r = 0; r < 4; r++)
#pragma unroll
        for (int c = 0; c < 4; c++) acc[r][c] = 0ull;

    for (int k0 = 0; k0 < K; k0 += 16) {
        // A tile 16x64 (coalesced float4 along M)
        {
            int kk = t >> 4, mf = t & 15;
            float4 v = *reinterpret_cast<const float4*>(
                &AT[(size_t)(k0 + kk) * MROWS + m0 + mf * 4]);
            *reinterpret_cast<float4*>(&As[kk][mf * 4]) = v;
        }
        // B tile 128x16, transposed into smem
#pragma unroll
        for (int i = 0; i < 2; i++) {
            int l  = t + i * 256;
            int kw = l & 3, nn = l >> 2;
            int n  = n0 + nn;
            float4 v = make_float4(0.f, 0.f, 0.f, 0.f);
            if (n < N)
                v = *reinterpret_cast<const float4*>(&W[(size_t)n * K + k0 + kw * 4]);
            Bs[kw*4+0][nn] = v.x;
            Bs[kw*4+1][nn] = v.y;
            Bs[kw*4+2][nn] = v.z;
            Bs[kw*4+3][nn] = v.w;
        }
        __syncthreads();
#pragma unroll
        for (int kk = 0; kk < 16; kk++) {
            float4 a4 = *reinterpret_cast<const float4*>(&As[kk][ty * 4]);
            ulonglong2 b01 = *reinterpret_cast<const ulonglong2*>(&Bs[kk][tx * 8]);
            ulonglong2 b23 = *reinterpret_cast<const ulonglong2*>(&Bs[kk][tx * 8 + 4]);
            unsigned long long a2[4];
            asm("mov.b64 %0, {%1, %1};" : "=l"(a2[0]) : "f"(a4.x));
            asm("mov.b64 %0, {%1, %1};" : "=l"(a2[1]) : "f"(a4.y));
            asm("mov.b64 %0, {%1, %1};" : "=l"(a2[2]) : "f"(a4.z));
            asm("mov.b64 %0, {%1, %1};" : "=l"(a2[3]) : "f"(a4.w));
#pragma unroll
            for (int r = 0; r < 4; r++) {
                asm("fma.rn.f32x2 %0, %1, %2, %0;" : "+l"(acc[r][0]) : "l"(a2[r]), "l"(b01.x));
                asm("fma.rn.f32x2 %0, %1, %2, %0;" : "+l"(acc[r][1]) : "l"(a2[r]), "l"(b01.y));
                asm("fma.rn.f32x2 %0, %1, %2, %0;" : "+l"(acc[r][2]) : "l"(a2[r]), "l"(b23.x));
                asm("fma.rn.f32x2 %0, %1, %2, %0;" : "+l"(acc[r][3]) : "l"(a2[r]), "l"(b23.y));
            }
        }
        __syncthreads();
    }
#pragma unroll
    for (int r = 0; r < 4; r++) {
        int m = m0 + ty * 4 + r;   // MROWS divisible by 64 -> always valid
#pragma unroll
        for (int c = 0; c < 4; c++) {
            float lo, hi;
            asm("mov.b64 {%0, %1}, %2;" : "=f"(lo), "=f"(hi) : "l"(acc[r][c]));
            int n = n0 + tx * 8 + c * 2;
            if (n < N) {
                float v0 = lo + bias[n];
                if (TRANS_OUT) C[(size_t)n * MROWS + m] = v0;
                else           C[(size_t)m * N + n]     = v0;
            }
            if (n + 1 < N) {
                float v1 = hi + bias[n + 1];
                if (TRANS_OUT) C[(size_t)(n + 1) * MROWS + m] = v1;
                else           C[(size_t)m * N + n + 1]       = v1;
            }
        }
    }
}

// ---------------- assemble proposals + scores ----------------
__global__ void k_assemble(const float* __restrict__ anchd, float* __restrict__ out) {
    int row = blockIdx.x;            // b*42+e
    int b = row / NEDGE, e = row % NEDGE;
    float* prop   = out + (size_t)b * NPROP * NPRED;
    float* scores = out + (size_t)NB * NPROP * NPRED + (size_t)NB * NPROP + (size_t)b * NPROP;
    for (int l = threadIdx.x; l < NANG * NPRED; l += blockDim.x) {
        int a = l / NPRED, q = l % NPRED;
        int p = e * NANG + a;
        float v;
        if (q < 2)      v = g_cls[(size_t)row * NCLS + a * 2 + q];
        else if (q < 4) v = anchd[(size_t)p * NPRED + q];
        else            v = anchd[(size_t)p * NPRED + q]
                            + g_reg[(size_t)row * NREG + a * 73 + (q - 4)];
        prop[(size_t)p * NPRED + q] = v;
    }
    if (threadIdx.x < NANG) {
        int a = threadIdx.x;
        int p = e * NANG + a;
        float l0 = g_cls[(size_t)row * NCLS + a * 2];
        float l1 = g_cls[(size_t)row * NCLS + a * 2 + 1];
        scores[p] = 1.0f / (1.0f + expf(l0 - l1));   // softmax(...)[1]
    }
}

// ---------------- NMS: stable descending argsort + sorted gather ----------------
__global__ void k_sort(const float* __restrict__ out) {
    int b = blockIdx.x;
    __shared__ float s[NPROP];
    const float* scores = out + (size_t)NB * NPROP * NPRED + (size_t)NB * NPROP + (size_t)b * NPROP;
    const float* prop   = out + (size_t)b * NPROP * NPRED;
    for (int i = threadIdx.x; i < NPROP; i += blockDim.x) s[i] = scores[i];
    __syncthreads();
    for (int i = threadIdx.x; i < NPROP; i += blockDim.x) {
        float si = s[i];
        int r = 0;
        for (int j = 0; j < NPROP; j++) {
            float sj = s[j];
            r += (sj > si) || (sj == si && j < i);   // stable, descending
        }
        int base = b * NPROP + r;
        g_order[base] = i;
        float p2 = prop[(size_t)i * NPRED + 2];
        float p4 = prop[(size_t)i * NPRED + 4];
        float st = fminf(fmaxf(rintf(p2 * NSTRIPSF), 0.0f), NSTRIPSF);  // round-half-even == jnp.round
        float en = fminf(fmaxf(st + p4 - 1.0f, 0.0f), NSTRIPSF);
        g_sstart[base] = st;
        g_send[base]   = en;
        float* dst = g_sxs + (size_t)base * NOFF;
        const float* src = prop + (size_t)i * NPRED + 5;
        for (int k = 0; k < NOFF; k++) dst[k] = src[k];
    }
}

// ---------------- NMS: pairwise suppression bitmatrix ----------------
__global__ void k_pairs() {
    int b    = blockIdx.y;
    int warp = threadIdx.x >> 5;
    int lane = threadIdx.x & 31;
    int i    = blockIdx.x * 8 + warp;
    if (i >= NPROP) return;
    int base = b * NPROP;
    float si = g_sstart[base + i], ei = g_send[base + i];
    const float* xi = g_sxs + (size_t)(base + i) * NOFF;
    for (int jw = 0; jw < NWORDS; jw++) {
        int j = jw * 32 + lane;
        bool sup = false;
        if (j < NPROP) {
            float s  = fmaxf(si, g_sstart[base + j]);
            float e  = fminf(ei, g_send[base + j]);
            float cnt = e - s + 1.0f;
            if (cnt > 0.0f) {
                const float* xj = g_sxs + (size_t)(base + j) * NOFF;
                int k0 = (int)s;             // starts are integral after clip
                int k1 = (int)floorf(e);     // k <= e
                float sum = 0.0f;
                for (int k = k0; k <= k1; k++) sum += fabsf(xi[k] - xj[k]);
                sup = (sum / fmaxf(cnt, 1.0f)) < NMS_T;
            }
        }
        unsigned m = __ballot_sync(0xFFFFFFFFu, sup);
        if (lane == 0) g_sup[(size_t)(base + i) * NWORDS + jw] = m;
    }
}

// ---------------- NMS: sequential scan (one warp per batch) ----------------
__global__ void k_scan(float* __restrict__ out) {
    int b    = blockIdx.x;
    int lane = threadIdx.x;
    float* keep = out + (size_t)NB * NPROP * NPRED + (size_t)b * NPROP;
    int base = b * NPROP;
    unsigned my = 0;  // lane l owns suppressed-bit word l (l < NWORDS)
    unsigned row_next = (lane < NWORDS) ? g_sup[(size_t)base * NWORDS + lane] : 0u;
    for (int i = 0; i < NPROP; i++) {
        unsigned row = row_next;
        if (i + 1 < NPROP && lane < NWORDS)
            row_next = g_sup[(size_t)(base + i + 1) * NWORDS + lane];
        int wi = i >> 5, bit = i & 31;
        unsigned wsup = __shfl_sync(0xFFFFFFFFu, my, wi);
        bool kept = ((wsup >> bit) & 1u) == 0u;
        if (kept) {
            unsigned m;
            if (lane > wi)       m = 0xFFFFFFFFu;
            else if (lane == wi) m = (bit == 31) ? 0u : (0xFFFFFFFFu << (bit + 1));
            else                 m = 0u;
            my |= row & m;       // suppress only j > i
        }
        if (lane == 0) keep[g_order[base + i]] = kept ? 1.0f : 0.0f;
    }
}

// ---------------- launcher ----------------
extern "C" void kernel_launch(void* const* d_in, const int* in_sizes, int n_in,
                              void* d_out, int out_size) {
    const float* feat   = (const float*)d_in[0];
    const float* W_conv = (const float*)d_in[1];
    const float* b_conv = (const float*)d_in[2];
    const float* W_cls  = (const float*)d_in[3];
    const float* b_cls  = (const float*)d_in[4];
    const float* W_reg  = (const float*)d_in[5];
    const float* b_reg  = (const float*)d_in[6];
    // d_in[7] = anchors (full grid, unused)
    const float* anchd  = (const float*)d_in[8];
    float* out = (float*)d_out;

    void *p_featET, *p_convT, *p_reg, *p_cls;
    cudaGetSymbolAddress(&p_featET, g_featET);
    cudaGetSymbolAddress(&p_convT,  g_convT);
    cudaGetSymbolAddress(&p_reg,    g_reg);
    cudaGetSymbolAddress(&p_cls,    g_cls);

    k_gather<<<(KBACK * MROWS + 255) / 256, 256>>>(feat);
    k_gemm<1><<<dim3(KCONV / 128, MROWS / 64), 256>>>(
        (const float*)p_featET, W_conv, b_conv, (float*)p_convT, KBACK, KCONV);
    k_gemm<0><<<dim3((NREG + 127) / 128, MROWS / 64), 256>>>(
        (const float*)p_convT, W_reg, b_reg, (float*)p_reg, KCONV, NREG);
    k_gemm<0><<<dim3(1, MROWS / 64), 256>>>(
        (const float*)p_convT, W_cls, b_cls, (float*)p_cls, KCONV, NCLS);
    k_assemble<<<MROWS, 256>>>(anchd, out);
    k_sort<<<NB, 256>>>(out);
    k_pairs<<<dim3((NPROP + 7) / 8, NB), 256>>>();
    k_scan<<<NB, 32>>>(out);
}